// round 11
// baseline (speedup 1.0000x reference)
#include <cuda_runtime.h>
#include <cstdint>

// ---------------------------------------------------------------------------
// y[m, n*410+f] = u[m,f] + sx[m,n]*G[n,f] + c[f]
//   U[:, 0:410] = X @ Wfc^T,  U[:, 410:420] = X @ Wsel^T  (one tf32 GEMM)
//   G = Wfc @ Wexp, c = Wfc @ bexp + bfc
// GEMM: BM=64 / BN=112, 128 thr, 4 warps (2x2) of 32x56, cp.async 4-stage
// ring (90KB smem) -> TWO blocks per SM = 2 independent warps/SMSP filling
// issue/latency gaps while crossbar stays under the tensor floor.
// B pre-converted to tf32 in prep (g_Bt, 0-pad).
// r10 bug fixed: ldsm2 address uses the validated hB half-select form.
// ---------------------------------------------------------------------------

#define KDIM    4096
#define NFC     410
#define NCOLS   420
#define NBT     448
#define USTRIDE 432
#define MMAX    4096

#define BM 64
#define BN 112
#define BK 32
#define NKT (KDIM / BK)              // 128
#define STAGES 4
#define TILE_A  (BM * BK * 4)        // 8192
#define TILE_B  (BN * BK * 4)        // 14336
#define STAGE_BYTES (TILE_A + TILE_B) // 22528

#define KSPLIT 8
#define PREPW  4576

__device__ float g_U[MMAX * USTRIDE];
__device__ float g_G[10 * 416];
__device__ float g_c[416];
__device__ float g_part[KSPLIT][PREPW];
__device__ float g_Bt[NBT * KDIM];     // tf32-converted B (Wfc | Wsel | 0-pad)

// ---------------- helpers ----------------------------------------------------
__device__ __forceinline__ uint32_t smem_u32(const void* p) {
    uint32_t a;
    asm("{ .reg .u64 t; cvta.to.shared.u64 t, %1; cvt.u32.u64 %0, t; }" : "=r"(a) : "l"(p));
    return a;
}
__device__ __forceinline__ void cp16(uint32_t dst, const void* src) {
    asm volatile("cp.async.cg.shared.global [%0], [%1], 16;"
                 :: "r"(dst), "l"(src) : "memory");
}
__device__ __forceinline__ void cp_commit() {
    asm volatile("cp.async.commit_group;" ::: "memory");
}
__device__ __forceinline__ void cp_wait2() {
    asm volatile("cp.async.wait_group 2;" ::: "memory");
}
__device__ __forceinline__ void ldsm4(uint32_t* r, uint32_t a) {
    asm volatile("ldmatrix.sync.aligned.m8n8.x4.shared.b16 {%0,%1,%2,%3}, [%4];"
                 : "=r"(r[0]), "=r"(r[1]), "=r"(r[2]), "=r"(r[3]) : "r"(a));
}
__device__ __forceinline__ void ldsm2(uint32_t* r, uint32_t a) {
    asm volatile("ldmatrix.sync.aligned.m8n8.x2.shared.b16 {%0,%1}, [%2];"
                 : "=r"(r[0]), "=r"(r[1]) : "r"(a));
}
__device__ __forceinline__ uint32_t f2tf(uint32_t v) {
    uint32_t r;
    asm("cvt.rna.tf32.f32 %0, %1;" : "=r"(r) : "f"(__uint_as_float(v)));
    return r;
}
__device__ __forceinline__ float f2tf_f(float v) {
    uint32_t r;
    asm("cvt.rna.tf32.f32 %0, %1;" : "=r"(r) : "f"(v));
    return __uint_as_float(r);
}
__device__ __forceinline__ void mma8(float* c, const uint32_t* a, const uint32_t* b) {
    asm volatile(
        "mma.sync.aligned.m16n8k8.row.col.f32.tf32.tf32.f32 "
        "{%0,%1,%2,%3}, {%4,%5,%6,%7}, {%8,%9}, {%0,%1,%2,%3};"
        : "+f"(c[0]), "+f"(c[1]), "+f"(c[2]), "+f"(c[3])
        : "r"(a[0]), "r"(a[1]), "r"(a[2]), "r"(a[3]), "r"(b[0]), "r"(b[1]));
}

// ---------------------------------------------------------------------------
// prep pass 1: G/c partials (f<410) + tf32 B materialization (all f<448)
// ---------------------------------------------------------------------------
__global__ void prep_part(const float* __restrict__ Wfc, const float* __restrict__ Wsel,
                          const float* __restrict__ Wexp, const float* __restrict__ bexp) {
    int f  = blockIdx.x;                 // 0..447
    int kz = blockIdx.y;
    int k0 = kz * 512;
    const float* src = nullptr;
    if (f < NFC)        src = Wfc + (size_t)f * KDIM + k0;
    else if (f < NCOLS) src = Wsel + (size_t)(f - NFC) * KDIM + k0;

    float acc[11];
#pragma unroll
    for (int v = 0; v < 11; v++) acc[v] = 0.f;

#pragma unroll
    for (int it = 0; it < 4; it++) {
        int k = it * 128 + threadIdx.x;
        float w = src ? src[k] : 0.f;
        g_Bt[(size_t)f * KDIM + k0 + k] = f2tf_f(w);
        if (f < NFC) {
            const float* we = Wexp + (size_t)(k0 + k) * 10;
#pragma unroll
            for (int n = 0; n < 10; n++) acc[n] += w * we[n];
            acc[10] += w * bexp[k0 + k];
        }
    }
    if (f >= NFC) return;

    __shared__ float red[4][11];
    int lane = threadIdx.x & 31, warp = threadIdx.x >> 5;
#pragma unroll
    for (int v = 0; v < 11; v++) {
        float s = acc[v];
#pragma unroll
        for (int o = 16; o; o >>= 1) s += __shfl_xor_sync(0xffffffffu, s, o);
        if (lane == 0) red[warp][v] = s;
    }
    __syncthreads();
    if (threadIdx.x < 11) {
        float s = red[0][threadIdx.x] + red[1][threadIdx.x] +
                  red[2][threadIdx.x] + red[3][threadIdx.x];
        g_part[kz][threadIdx.x * 416 + f] = s;
    }
}

__global__ void prep_combine(const float* __restrict__ bfc) {
    int i = blockIdx.x * 256 + threadIdx.x;
    if (i >= PREPW) return;
    float s = 0.f;
#pragma unroll
    for (int kz = 0; kz < KSPLIT; kz++) s += g_part[kz][i];
    if (i < 10 * 416) {
        g_G[i] = s;
    } else {
        int f = i - 10 * 416;
        g_c[f] = (f < NFC) ? s + bfc[f] : s;
    }
}

// ---------------------------------------------------------------------------
// GEMM: 64x112 block, 4 warps (2x2) of 32x56; B pre-converted; 2 blocks/SM
// ---------------------------------------------------------------------------
__global__ __launch_bounds__(128, 2)
void gemm_kernel(const float* __restrict__ x) {
    extern __shared__ char dyn[];
    char* bufs = (char*)(((uintptr_t)dyn + 1023) & ~(uintptr_t)1023);
    const uint32_t bufs_u32 = smem_u32(bufs);

    const int tid  = threadIdx.x;
    const int lane = tid & 31;
    const int warp = tid >> 5;
    const int wm   = warp >> 1;        // 0..1
    const int wn   = warp & 1;         // 0..1
    const int m0   = blockIdx.y * BM;
    const int n0   = blockIdx.x * BN;

    // ---- A loader: row tid>>1 (0..63), 4 consecutive chunks ----
    const int arow = tid >> 1;
    const int ac0  = (tid & 1) * 4;
    uint32_t adst[4];
#pragma unroll
    for (int i = 0; i < 4; i++)
        adst[i] = (uint32_t)(arow * 128 + (((ac0 + i) * 16) ^ ((arow & 7) << 4)));
    const char* aglob = (const char*)(x + (size_t)(m0 + arow) * KDIM + ac0 * 4);

    // ---- B loader: rows tid>>3 (+16i, 7 slabs), chunk tid&7 ----
    const int brow = tid >> 3;
    const int bq   = tid & 7;
    const uint32_t bdst = (uint32_t)(brow * 128 + ((bq * 16) ^ ((brow & 7) << 4)));
    const char* bglob = (const char*)(g_Bt + (size_t)(n0 + brow) * KDIM + bq * 4);

    auto issue = [&](int kt) {
        int stage = kt & (STAGES - 1);
        uint32_t sb = bufs_u32 + stage * STAGE_BYTES;
        const char* as = aglob + (size_t)kt * 128;
        const char* bs = bglob + (size_t)kt * 128;
#pragma unroll
        for (int i = 0; i < 4; i++) cp16(sb + adst[i], as + i * 16);
#pragma unroll
        for (int i = 0; i < 7; i++)
            cp16(sb + TILE_A + bdst + i * 2048, bs + (size_t)i * (16 * KDIM * 4));
    };

    // ---- fragment constants ----
    const uint32_t aoff  = (uint32_t)((wm * 32 + (lane & 15)) * 128);
    const uint32_t xS    = (uint32_t)((lane & 7) << 4);
    const uint32_t hA    = (lane & 16) ? 16u : 0u;
    const uint32_t boffp = (uint32_t)((wn * 56 + (lane & 7) + ((lane & 16) ? 8 : 0)) * 128);
    const uint32_t boff2 = (uint32_t)((wn * 56 + 48 + (lane & 7)) * 128);
    const uint32_t hB    = (lane & 8) ? 16u : 0u;

    float acc[2][7][4];
#pragma unroll
    for (int mi = 0; mi < 2; mi++)
#pragma unroll
        for (int nj = 0; nj < 7; nj++)
#pragma unroll
            for (int q = 0; q < 4; q++) acc[mi][nj][q] = 0.f;

    issue(0); cp_commit();
    issue(1); cp_commit();
    issue(2); cp_commit();

    uint32_t a[2][2][4], bp[2][3][4], b6[2][2];

#pragma unroll 1
    for (int kt = 0; kt < NKT; kt++) {
        cp_wait2();
        __syncthreads();
        if (kt + 3 < NKT) issue(kt + 3);
        cp_commit();

        const uint32_t As = bufs_u32 + (kt & (STAGES - 1)) * STAGE_BYTES;
        const uint32_t Bs = As + TILE_A;

        // preload ks=0 (ldsm2 uses the SAME validated hB half-select as ldsm4)
        {
            const uint32_t ka = hA ^ xS;
            const uint32_t kb = hB ^ xS;
#pragma unroll
            for (int mi = 0; mi < 2; mi++) ldsm4(a[0][mi], As + aoff + mi * 2048 + ka);
#pragma unroll
            for (int p = 0; p < 3; p++)   ldsm4(bp[0][p], Bs + boffp + p * 2048 + kb);
            ldsm2(b6[0], Bs + boff2 + kb);
#pragma unroll
            for (int mi = 0; mi < 2; mi++)
#pragma unroll
                for (int q = 0; q < 4; q++) a[0][mi][q] = f2tf(a[0][mi][q]);
        }

#pragma unroll
        for (int ks = 0; ks < 4; ks++) {
            const int cur = ks & 1;
            const int nxt = cur ^ 1;
            if (ks < 3) {
                const uint32_t ka = (uint32_t)((ks + 1) * 32 + hA) ^ xS;
                const uint32_t kb = (uint32_t)((ks + 1) * 32 + hB) ^ xS;
#pragma unroll
                for (int mi = 0; mi < 2; mi++) ldsm4(a[nxt][mi], As + aoff + mi * 2048 + ka);
#pragma unroll
                for (int p = 0; p < 3; p++)   ldsm4(bp[nxt][p], Bs + boffp + p * 2048 + kb);
                ldsm2(b6[nxt], Bs + boff2 + kb);
            }
#pragma unroll
            for (int mi = 0; mi < 2; mi++) {
#pragma unroll
                for (int p = 0; p < 3; p++) {
                    mma8(acc[mi][2 * p],     a[cur][mi], &bp[cur][p][0]);
                    mma8(acc[mi][2 * p + 1], a[cur][mi], &bp[cur][p][2]);
                }
                mma8(acc[mi][6], a[cur][mi], b6[cur]);
            }
            if (ks < 3) {
#pragma unroll
                for (int mi = 0; mi < 2; mi++)
#pragma unroll
                    for (int q = 0; q < 4; q++) a[nxt][mi][q] = f2tf(a[nxt][mi][q]);
            }
        }
    }

    // ---- write U (guard pad columns) ----
    const int gid = lane >> 2;
    const int tig = lane & 3;
#pragma unroll
    for (int mi = 0; mi < 2; mi++) {
        int r0 = m0 + wm * 32 + mi * 16 + gid;
#pragma unroll
        for (int nj = 0; nj < 7; nj++) {
            int col = n0 + wn * 56 + nj * 8 + 2 * tig;
            if (col < NCOLS) {
                *reinterpret_cast<float2*>(&g_U[(size_t)r0 * USTRIDE + col]) =
                    make_float2(acc[mi][nj][0], acc[mi][nj][1]);
                *reinterpret_cast<float2*>(&g_U[(size_t)(r0 + 8) * USTRIDE + col]) =
                    make_float2(acc[mi][nj][2], acc[mi][nj][3]);
            }
        }
    }
}

// ---------------------------------------------------------------------------
// epilogue: 1 row/block, float4 loads; float4 stores where base%4==0,
// 2x float2 where base%4==2; scalar tail per segment.
// ---------------------------------------------------------------------------
__global__ void epi_kernel(const float* __restrict__ bsel, float* __restrict__ out) {
    int m = blockIdx.x;
    __shared__ float sx[10];
    if (threadIdx.x < 10)
        sx[threadIdx.x] = g_U[(size_t)m * USTRIDE + NFC + threadIdx.x] + bsel[threadIdx.x];
    __syncthreads();
    const float* Ur = g_U + (size_t)m * USTRIDE;
    float* orow = out + (size_t)m * 4096;
#pragma unroll 1
    for (int n = 0; n < 10; n++) {
        int base = n * NFC;
        float sxn = sx[n];
        int lim = (n == 9) ? (4096 - base) : NFC;   // 410 or 406
        int body = lim & ~3;                        // 408 or 404
        const float* Gn = g_G + n * 416;
        for (int f = threadIdx.x * 4; f < body; f += 1024) {
            float4 u  = *reinterpret_cast<const float4*>(Ur + f);
            float4 gg = *reinterpret_cast<const float4*>(Gn + f);
            float4 cc = *reinterpret_cast<const float4*>(g_c + f);
            float4 r;
            r.x = fmaf(sxn, gg.x, u.x + cc.x);
            r.y = fmaf(sxn, gg.y, u.y + cc.y);
            r.z = fmaf(sxn, gg.z, u.z + cc.z);
            r.w = fmaf(sxn, gg.w, u.w + cc.w);
            if (base & 2) {
                *reinterpret_cast<float2*>(orow + base + f)     = make_float2(r.x, r.y);
                *reinterpret_cast<float2*>(orow + base + f + 2) = make_float2(r.z, r.w);
            } else {
                *reinterpret_cast<float4*>(orow + base + f) = r;
            }
        }
        if (threadIdx.x < lim - body) {
            int f = body + threadIdx.x;
            orow[base + f] = fmaf(sxn, Gn[f], Ur[f] + g_c[f]);
        }
    }
}

// ---------------------------------------------------------------------------
extern "C" void kernel_launch(void* const* d_in, const int* in_sizes, int n_in,
                              void* d_out, int out_size) {
    const float* x    = (const float*)d_in[0];
    const float* Wsel = (const float*)d_in[1];
    const float* bsel = (const float*)d_in[2];
    const float* Wexp = (const float*)d_in[3];
    const float* bexp = (const float*)d_in[4];
    const float* Wfc  = (const float*)d_in[5];
    const float* bfc  = (const float*)d_in[6];
    float* out = (float*)d_out;

    int M = in_sizes[0] / KDIM;   // 4096

    const int smem_bytes = STAGES * STAGE_BYTES + 1024;   // 91136 -> 2 blocks/SM
    cudaFuncSetAttribute(gemm_kernel, cudaFuncAttributeMaxDynamicSharedMemorySize, smem_bytes);

    prep_part<<<dim3(NBT, KSPLIT), 128>>>(Wfc, Wsel, Wexp, bexp);
    prep_combine<<<(PREPW + 255) / 256, 256>>>(bfc);
    dim3 grid(4, M / BM);   // 4 x 64 = 256 blocks
    gemm_kernel<<<grid, 128, smem_bytes>>>(x);
    epi_kernel<<<M, 256>>>(bsel, out);
}

// round 12
// speedup vs baseline: 1.4011x; 1.4011x over previous
#include <cuda_runtime.h>
#include <cuda_fp16.h>
#include <cstdint>

// ---------------------------------------------------------------------------
// y[m, n*410+f] = u[m,f] + sx[m,n]*G[n,f] + c[f]
//   U[:, 0:410] = X @ Wfc^T,  U[:, 410:420] = X @ Wsel^T  (one fp16 GEMM)
//   G = Wfc @ Wexp, c = Wfc @ bexp + bfc
// GEMM: mma.sync m16n8k16 fp16 (same 10 mantissa bits as tf32; 2x MAC/HMMA).
// r9 schedule kept verbatim: 128 thr, 4 warps of 32x112, BN=112, cp.async
// 4-stage ring, identical swizzle/fragment addressing (BK=64 fp16 = 128B rows).
// A pre-converted to fp16 (g_xh), B pre-converted in prep (g_Bt) -> ZERO cvt
// in the mainloop.
// ---------------------------------------------------------------------------

#define KDIM    4096
#define NFC     410
#define NCOLS   420
#define NBT     448
#define USTRIDE 432
#define MMAX    4096

#define BM 128
#define BN 112
#define BK 64                        // fp16 elems -> 128 bytes per smem row
#define NKT (KDIM / BK)              // 64
#define STAGES 4
#define TILE_A  (BM * BK * 2)        // 16384
#define TILE_B  (BN * BK * 2)        // 14336
#define STAGE_BYTES (TILE_A + TILE_B) // 30720

#define KSPLIT 8
#define PREPW  4576

__device__ float  g_U[MMAX * USTRIDE];
__device__ float  g_G[10 * 416];
__device__ float  g_c[416];
__device__ float  g_part[KSPLIT][PREPW];
__device__ __half g_Bt[NBT * KDIM];    // fp16 B (Wfc | Wsel | 0-pad)
__device__ __half g_xh[MMAX * KDIM];   // fp16 X

// ---------------- helpers ----------------------------------------------------
__device__ __forceinline__ uint32_t smem_u32(const void* p) {
    uint32_t a;
    asm("{ .reg .u64 t; cvta.to.shared.u64 t, %1; cvt.u32.u64 %0, t; }" : "=r"(a) : "l"(p));
    return a;
}
__device__ __forceinline__ void cp16(uint32_t dst, const void* src) {
    asm volatile("cp.async.cg.shared.global [%0], [%1], 16;"
                 :: "r"(dst), "l"(src) : "memory");
}
__device__ __forceinline__ void cp_commit() {
    asm volatile("cp.async.commit_group;" ::: "memory");
}
__device__ __forceinline__ void cp_wait2() {
    asm volatile("cp.async.wait_group 2;" ::: "memory");
}
__device__ __forceinline__ void ldsm4(uint32_t* r, uint32_t a) {
    asm volatile("ldmatrix.sync.aligned.m8n8.x4.shared.b16 {%0,%1,%2,%3}, [%4];"
                 : "=r"(r[0]), "=r"(r[1]), "=r"(r[2]), "=r"(r[3]) : "r"(a));
}
__device__ __forceinline__ void mma16(float* c, const uint32_t* a, const uint32_t* b) {
    asm volatile(
        "mma.sync.aligned.m16n8k16.row.col.f32.f16.f16.f32 "
        "{%0,%1,%2,%3}, {%4,%5,%6,%7}, {%8,%9}, {%0,%1,%2,%3};"
        : "+f"(c[0]), "+f"(c[1]), "+f"(c[2]), "+f"(c[3])
        : "r"(a[0]), "r"(a[1]), "r"(a[2]), "r"(a[3]), "r"(b[0]), "r"(b[1]));
}

// ---------------------------------------------------------------------------
// x -> fp16 (8 elems/thread, vectorized)
// ---------------------------------------------------------------------------
__global__ void xh_kernel(const float* __restrict__ x) {
    int i = (blockIdx.x * 256 + threadIdx.x) * 8;
    float4 v0 = *reinterpret_cast<const float4*>(x + i);
    float4 v1 = *reinterpret_cast<const float4*>(x + i + 4);
    __half2 h0 = __floats2half2_rn(v0.x, v0.y);
    __half2 h1 = __floats2half2_rn(v0.z, v0.w);
    __half2 h2 = __floats2half2_rn(v1.x, v1.y);
    __half2 h3 = __floats2half2_rn(v1.z, v1.w);
    uint4 pk;
    pk.x = *reinterpret_cast<uint32_t*>(&h0);
    pk.y = *reinterpret_cast<uint32_t*>(&h1);
    pk.z = *reinterpret_cast<uint32_t*>(&h2);
    pk.w = *reinterpret_cast<uint32_t*>(&h3);
    *reinterpret_cast<uint4*>(g_xh + i) = pk;
}

// ---------------------------------------------------------------------------
// prep pass 1: G/c partials (f<410) + fp16 B materialization (all f<448)
// ---------------------------------------------------------------------------
__global__ void prep_part(const float* __restrict__ Wfc, const float* __restrict__ Wsel,
                          const float* __restrict__ Wexp, const float* __restrict__ bexp) {
    int f  = blockIdx.x;                 // 0..447
    int kz = blockIdx.y;
    int k0 = kz * 512;
    const float* src = nullptr;
    if (f < NFC)        src = Wfc + (size_t)f * KDIM + k0;
    else if (f < NCOLS) src = Wsel + (size_t)(f - NFC) * KDIM + k0;

    float acc[11];
#pragma unroll
    for (int v = 0; v < 11; v++) acc[v] = 0.f;

#pragma unroll
    for (int it = 0; it < 4; it++) {
        int k = it * 128 + threadIdx.x;
        float w = src ? src[k] : 0.f;
        g_Bt[(size_t)f * KDIM + k0 + k] = __float2half_rn(w);
        if (f < NFC) {
            const float* we = Wexp + (size_t)(k0 + k) * 10;
#pragma unroll
            for (int n = 0; n < 10; n++) acc[n] += w * we[n];
            acc[10] += w * bexp[k0 + k];
        }
    }
    if (f >= NFC) return;

    __shared__ float red[4][11];
    int lane = threadIdx.x & 31, warp = threadIdx.x >> 5;
#pragma unroll
    for (int v = 0; v < 11; v++) {
        float s = acc[v];
#pragma unroll
        for (int o = 16; o; o >>= 1) s += __shfl_xor_sync(0xffffffffu, s, o);
        if (lane == 0) red[warp][v] = s;
    }
    __syncthreads();
    if (threadIdx.x < 11) {
        float s = red[0][threadIdx.x] + red[1][threadIdx.x] +
                  red[2][threadIdx.x] + red[3][threadIdx.x];
        g_part[kz][threadIdx.x * 416 + f] = s;
    }
}

__global__ void prep_combine(const float* __restrict__ bfc) {
    int i = blockIdx.x * 256 + threadIdx.x;
    if (i >= PREPW) return;
    float s = 0.f;
#pragma unroll
    for (int kz = 0; kz < KSPLIT; kz++) s += g_part[kz][i];
    if (i < 10 * 416) {
        g_G[i] = s;
    } else {
        int f = i - 10 * 416;
        g_c[f] = (f < NFC) ? s + bfc[f] : s;
    }
}

// ---------------------------------------------------------------------------
// GEMM: 128x112 block, 4 warps (4wm x 1wn) of 32x112, fp16 m16n8k16
// ---------------------------------------------------------------------------
__global__ __launch_bounds__(128, 1)
void gemm_kernel() {
    extern __shared__ char dyn[];
    char* bufs = (char*)(((uintptr_t)dyn + 1023) & ~(uintptr_t)1023);
    const uint32_t bufs_u32 = smem_u32(bufs);

    const int tid  = threadIdx.x;
    const int lane = tid & 31;
    const int warp = tid >> 5;         // wm 0..3, single wn
    const int m0   = blockIdx.y * BM;
    const int n0   = blockIdx.x * BN;

    // ---- loader: lrow 0..15 (+16i), 16B chunk lq ----
    const int lrow = tid >> 3;
    const int lq   = tid & 7;
    const uint32_t dstoff = (uint32_t)(lrow * 128 + ((lq * 16) ^ ((lrow & 7) << 4)));
    const char* aglob = (const char*)(g_xh + (size_t)(m0 + lrow) * KDIM) + lq * 16;
    const char* bglob = (const char*)(g_Bt + (size_t)(n0 + lrow) * KDIM) + lq * 16;

    auto issue = [&](int kt) {
        int stage = kt & (STAGES - 1);
        uint32_t ad = bufs_u32 + stage * STAGE_BYTES + dstoff;
        uint32_t bd = ad + TILE_A;
        const char* as = aglob + (size_t)kt * 128;
        const char* bs = bglob + (size_t)kt * 128;
#pragma unroll
        for (int i = 0; i < 8; i++)
            cp16(ad + i * 2048, as + (size_t)i * (16 * KDIM * 2));
#pragma unroll
        for (int i = 0; i < 7; i++)
            cp16(bd + i * 2048, bs + (size_t)i * (16 * KDIM * 2));
    };

    // ---- fragment constants (identical structure to validated tf32 path) ----
    const uint32_t aoff = (uint32_t)((warp * 32 + (lane & 15)) * 128);
    const uint32_t xS   = (uint32_t)((lane & 7) << 4);
    const uint32_t hA   = (lane & 16) ? 16u : 0u;
    const uint32_t boff = (uint32_t)(((lane & 7) + ((lane & 16) ? 8 : 0)) * 128);
    const uint32_t hB   = (lane & 8) ? 16u : 0u;

    float acc[2][14][4];
#pragma unroll
    for (int mi = 0; mi < 2; mi++)
#pragma unroll
        for (int nj = 0; nj < 14; nj++)
#pragma unroll
            for (int q = 0; q < 4; q++) acc[mi][nj][q] = 0.f;

    issue(0); cp_commit();
    issue(1); cp_commit();
    issue(2); cp_commit();

    uint32_t a[2][2][4], b[2][7][4];   // double-buffered fp16x2 fragments

#pragma unroll 1
    for (int kt = 0; kt < NKT; kt++) {
        cp_wait2();
        __syncthreads();
        if (kt + 3 < NKT) issue(kt + 3);
        cp_commit();

        const uint32_t As = bufs_u32 + (kt & (STAGES - 1)) * STAGE_BYTES;
        const uint32_t Bs = As + TILE_A;

        // preload ks=0 (k16 chunk; 32B step per ks, 16B half-select)
        {
            const uint32_t ka = hA ^ xS;
            const uint32_t kb = hB ^ xS;
#pragma unroll
            for (int mi = 0; mi < 2; mi++) ldsm4(a[0][mi], As + aoff + mi * 2048 + ka);
#pragma unroll
            for (int p = 0; p < 7; p++)   ldsm4(b[0][p], Bs + boff + p * 2048 + kb);
        }

#pragma unroll
        for (int ks = 0; ks < 4; ks++) {
            const int cur = ks & 1;
            const int nxt = cur ^ 1;
            if (ks < 3) {
                const uint32_t ka = (uint32_t)((ks + 1) * 32 + hA) ^ xS;
                const uint32_t kb = (uint32_t)((ks + 1) * 32 + hB) ^ xS;
#pragma unroll
                for (int mi = 0; mi < 2; mi++) ldsm4(a[nxt][mi], As + aoff + mi * 2048 + ka);
#pragma unroll
                for (int p = 0; p < 7; p++)   ldsm4(b[nxt][p], Bs + boff + p * 2048 + kb);
            }
#pragma unroll
            for (int mi = 0; mi < 2; mi++)
#pragma unroll
                for (int p = 0; p < 7; p++) {
                    mma16(acc[mi][2 * p],     a[cur][mi], &b[cur][p][0]);
                    mma16(acc[mi][2 * p + 1], a[cur][mi], &b[cur][p][2]);
                }
        }
    }

    // ---- write U (guard pad columns) ----
    const int gid = lane >> 2;
    const int tig = lane & 3;
#pragma unroll
    for (int mi = 0; mi < 2; mi++) {
        int r0 = m0 + warp * 32 + mi * 16 + gid;
#pragma unroll
        for (int nj = 0; nj < 14; nj++) {
            int col = n0 + nj * 8 + 2 * tig;
            if (col < NCOLS) {
                *reinterpret_cast<float2*>(&g_U[(size_t)r0 * USTRIDE + col]) =
                    make_float2(acc[mi][nj][0], acc[mi][nj][1]);
                *reinterpret_cast<float2*>(&g_U[(size_t)(r0 + 8) * USTRIDE + col]) =
                    make_float2(acc[mi][nj][2], acc[mi][nj][3]);
            }
        }
    }
}

// ---------------------------------------------------------------------------
// epilogue (r9 version — fastest measured): float2, 1 row/block
// ---------------------------------------------------------------------------
__global__ void epi_kernel(const float* __restrict__ bsel, float* __restrict__ out) {
    int m = blockIdx.x;
    __shared__ float sx[10];
    if (threadIdx.x < 10)
        sx[threadIdx.x] = g_U[(size_t)m * USTRIDE + NFC + threadIdx.x] + bsel[threadIdx.x];
    __syncthreads();
    const float* Ur = g_U + (size_t)m * USTRIDE;
    float* orow = out + (size_t)m * 4096;
#pragma unroll 1
    for (int n = 0; n < 10; n++) {
        int base = n * NFC;
        float sxn = sx[n];
        int lim = (n == 9) ? (4096 - base) : NFC;
        const float* Gn = g_G + n * 416;
        for (int f = threadIdx.x * 2; f < lim; f += 512) {
            float2 u = *reinterpret_cast<const float2*>(Ur + f);
            float2 g = *reinterpret_cast<const float2*>(Gn + f);
            float2 cc = *reinterpret_cast<const float2*>(g_c + f);
            float2 r;
            r.x = fmaf(sxn, g.x, u.x + cc.x);
            r.y = fmaf(sxn, g.y, u.y + cc.y);
            *reinterpret_cast<float2*>(orow + base + f) = r;
        }
    }
}

// ---------------------------------------------------------------------------
extern "C" void kernel_launch(void* const* d_in, const int* in_sizes, int n_in,
                              void* d_out, int out_size) {
    const float* x    = (const float*)d_in[0];
    const float* Wsel = (const float*)d_in[1];
    const float* bsel = (const float*)d_in[2];
    const float* Wexp = (const float*)d_in[3];
    const float* bexp = (const float*)d_in[4];
    const float* Wfc  = (const float*)d_in[5];
    const float* bfc  = (const float*)d_in[6];
    float* out = (float*)d_out;

    int M = in_sizes[0] / KDIM;   // 4096

    const int smem_bytes = STAGES * STAGE_BYTES + 1024;   // 123904
    cudaFuncSetAttribute(gemm_kernel, cudaFuncAttributeMaxDynamicSharedMemorySize, smem_bytes);

    xh_kernel<<<(M * KDIM) / (256 * 8), 256>>>(x);
    prep_part<<<dim3(NBT, KSPLIT), 128>>>(Wfc, Wsel, Wexp, bexp);
    prep_combine<<<(PREPW + 255) / 256, 256>>>(bfc);
    dim3 grid(4, M / BM);   // 4 x 32 = 128 blocks
    gemm_kernel<<<grid, 128, smem_bytes>>>();
    epi_kernel<<<M, 256>>>(bsel, out);
}